// round 2
// baseline (speedup 1.0000x reference)
#include <cuda_runtime.h>
#include <math.h>

#define T_DATA 20000
#define SUB 16
#define TNO 200
#define ENO 2000
#define INO 500
#define CHUNK 32
#define PI_F 3.14159265358979323846f

// ---------------- device scratch (no allocs allowed) ----------------
__device__ float g_syn_e[T_DATA * SUB];
__device__ float g_syn_i[T_DATA * SUB];
__device__ float g_base[T_DATA * SUB];
__device__ float g_ekT[TNO * SUB];   // [j][s]
__device__ float g_ikT[TNO * SUB];   // [j][s]
__device__ float g_hkT[TNO * SUB];   // [j][s] hist kernel
__device__ unsigned char g_seg_e[ENO];
__device__ unsigned char g_seg_i[INO];
__device__ float g_cw[SUB * SUB];    // C_den[s][q] * exp(W_spk[q]) / tau[q]
__device__ float g_rowsum[SUB];
__device__ float g_rho[SUB];
__device__ float g_k0sum[SUB];       // sum_j hist_kern[s][j]
__device__ int   g_fast;

// ---------------- K0: setup (kernels, seg maps, constants, filters out) ----------------
__global__ void k_setup(const float* C_den, const float* C_syn_e, const float* C_syn_i,
                        const float* Tau_e, const float* Tau_i,
                        const float* W_e, const float* W_i,
                        const float* D_e, const float* D_i,
                        const float* Tau_spk, const float* W_spk,
                        const float* W_hist, float* out_filters)
{
    int tid = threadIdx.x;
    for (int idx = tid; idx < SUB * TNO; idx += blockDim.x) {
        int s = idx / TNO, j = idx % TNO;
        float t = (float)j;
        float te  = fmaxf(t - expf(D_e[s]), 0.f);
        float tte = te / expf(Tau_e[s]);
        float ek  = tte * expf(-tte) * expf(W_e[s]);
        float ti  = fmaxf(t - expf(D_i[s]), 0.f);
        float tti = ti / expf(Tau_i[s]);
        float ik  = -tti * expf(-tti) * expf(W_i[s]);
        float tts = t / expf(Tau_spk[s]);
        float sk  = tts * expf(-tts) * expf(W_spk[s]);
        float raw = 4.0f * logf(t + 1.0f);
        float hk = 0.f;
        for (int b = 0; b < 16; b++) {
            float phi = PI_F * 0.5f * (float)b;
            float v = 0.f;
            if (!(raw < phi - PI_F || raw > phi + PI_F))
                v = 0.5f * cosf(raw - phi) + 0.5f;
            hk += W_hist[s * 16 + b] * v;
        }
        g_ekT[j * SUB + s] = ek;
        g_ikT[j * SUB + s] = ik;
        g_hkT[j * SUB + s] = hk;
        out_filters[(0  + s) * TNO + j] = ek;
        out_filters[(16 + s) * TNO + j] = ik;
        out_filters[(32 + s) * TNO + j] = sk;
        out_filters[(48 + s) * TNO + j] = hk;
    }
    for (int e = tid; e < ENO; e += blockDim.x) {
        int seg = 0;
        for (int s = 0; s < SUB; s++) if (C_syn_e[s * ENO + e] > 0.5f) seg = s;
        g_seg_e[e] = (unsigned char)seg;
    }
    for (int e = tid; e < INO; e += blockDim.x) {
        int seg = 0;
        for (int s = 0; s < SUB; s++) if (C_syn_i[s * INO + e] > 0.5f) seg = s;
        g_seg_i[e] = (unsigned char)seg;
    }
    if (tid < SUB) {
        g_rho[tid] = expf(-1.0f / expf(Tau_spk[tid]));
    }
    if (tid < SUB * SUB) {
        int s = tid >> 4, q = tid & 15;
        g_cw[s * SUB + q] = C_den[s * SUB + q] * expf(W_spk[q]) / expf(Tau_spk[q]);
    }
    __syncthreads();
    if (tid < SUB) {
        int s = tid;
        float rs = 0.f;
        for (int q = 0; q < SUB; q++) rs += g_cw[s * SUB + q];
        g_rowsum[s] = rs;
        float ks = 0.f;
        for (int j = 0; j < TNO; j++) ks += g_hkT[j * SUB + s];
        g_k0sum[s] = ks;
    }
    if (tid == 0) {
        int fast = 1;
        float r0 = g_rho[0];
        for (int s = 1; s < SUB; s++) if (g_rho[s] != r0) fast = 0;
        g_fast = fast;
    }
}

// ---------------- K1: segment sums (HBM-bound, 200 MB) ----------------
#define SEG_ROWS 4
__global__ void k_segsum(const float* __restrict__ S_e, const float* __restrict__ S_i)
{
    __shared__ unsigned char sege[ENO];
    __shared__ unsigned char segi[INO];
    __shared__ float acc[SEG_ROWS][32];
    int tid = threadIdx.x;
    for (int e = tid; e < ENO; e += blockDim.x) sege[e] = g_seg_e[e];
    for (int e = tid; e < INO; e += blockDim.x) segi[e] = g_seg_i[e];
    if (tid < SEG_ROWS * 32) ((float*)acc)[tid] = 0.f;
    __syncthreads();
    int t0 = blockIdx.x * SEG_ROWS;
    for (int r = 0; r < SEG_ROWS; r++) {
        const float* re = S_e + (size_t)(t0 + r) * ENO;
        for (int e = tid; e < ENO; e += blockDim.x) {
            float v = re[e];
            if (v != 0.f) atomicAdd(&acc[r][sege[e]], v);
        }
        const float* ri = S_i + (size_t)(t0 + r) * INO;
        for (int e = tid; e < INO; e += blockDim.x) {
            float v = ri[e];
            if (v != 0.f) atomicAdd(&acc[r][16 + segi[e]], v);
        }
    }
    __syncthreads();
    if (tid < SEG_ROWS * 32) {
        int r = tid >> 5, q = tid & 31;
        if (q < 16) g_syn_e[(t0 + r) * SUB + q] = acc[r][q];
        else        g_syn_i[(t0 + r) * SUB + (q - 16)] = acc[r][q];   // FIXED: read i-slots 16..31
    }
}

// ---------------- K2: causal depthwise FIR + Theta -> base ----------------
#define TILE_T 128
__global__ void k_conv(const float* __restrict__ Theta)
{
    __shared__ float se[(TILE_T + TNO) * SUB];
    __shared__ float si[(TILE_T + TNO) * SUB];
    int t0 = blockIdx.x * TILE_T;
    int tid = threadIdx.x;
    // slab covers times t0-200 .. t0+126 (327 rows)
    for (int idx = tid; idx < 327 * SUB; idx += blockDim.x) {
        int r = idx / SUB, s = idx % SUB;
        int tt = t0 - 200 + r;
        float ve = 0.f, vi = 0.f;
        if (tt >= 0 && tt < T_DATA) {
            ve = g_syn_e[tt * SUB + s];
            vi = g_syn_i[tt * SUB + s];
        }
        se[idx] = ve;
        si[idx] = vi;
    }
    __syncthreads();
    int s = tid & 15, tg = tid >> 4;  // 16 thread-groups over t
    float th = Theta[s];
    float acc[8];
#pragma unroll
    for (int k = 0; k < 8; k++) acc[k] = th;
    for (int j = 0; j < TNO; j++) {
        float ke = g_ekT[j * SUB + s];
        float ki = g_ikT[j * SUB + s];
#pragma unroll
        for (int k = 0; k < 8; k++) {
            int tl = tg + k * 16;          // local t in [0,127]
            int row = tl + 199 - j;        // slab row for time t0+tl-1-j
            acc[k] += ke * se[row * SUB + s] + ki * si[row * SUB + s];
        }
    }
#pragma unroll
    for (int k = 0; k < 8; k++) {
        int t = t0 + tg + k * 16;
        if (t < T_DATA) g_base[t * SUB + s] = acc[k];
    }
}

// ---------------- K3: sequential thresholded scan (single CTA) ----------------
__global__ void __launch_bounds__(512, 1) k_scan(float* __restrict__ spk_out)
{
    __shared__ float k_sh[TNO * SUB];       // hist kernel [j][s]
    __shared__ unsigned ring[16 * SUB];     // spike bit ring: [word][s], 512 steps deep
    __shared__ float Zpre[CHUNK * SUB];     // precomputed zero-lag sums (lags > intra)
    __shared__ float base_sh[CHUNK * SUB];
    __shared__ float spikes_sh[CHUNK * SUB];
    __shared__ float cw_sh[SUB * 17];       // padded to kill bank conflicts
    __shared__ float rowsum_sh[SUB], k0_sh[SUB], rho_sh[SUB];
    __shared__ int fast_sh;

    int tid = threadIdx.x;
    for (int idx = tid; idx < TNO * SUB; idx += 512) k_sh[idx] = g_hkT[idx];
    if (tid < 256) {
        int s = tid >> 4, q = tid & 15;
        cw_sh[s * 17 + q] = g_cw[s * SUB + q];
        ring[tid] = 0u;
    }
    if (tid < SUB) {
        rowsum_sh[tid] = g_rowsum[tid];
        k0_sh[tid] = g_k0sum[tid];
        rho_sh[tid] = g_rho[tid];
    }
    if (tid == 0) fast_sh = g_fast;
    __syncthreads();

    // persistent scan state (warp 0, lanes 0..15)
    float MA = 0.f, MB = 0.f, A = 0.f, B = 0.f;
    float cwrow[16];
    if (tid < 16) {
#pragma unroll
        for (int q = 0; q < 16; q++) cwrow[q] = cw_sh[tid * 17 + q];
    }
    int i_pre = tid >> 4, s_pre = tid & 15;

    for (int c = 0; c < T_DATA / CHUNK; c++) {
        int t0 = c * CHUNK;
        // ---- parallel pre-phase: Zpre[i][s] = sum of hist_kern over NON-spike lags m in [i+1,200] ----
        {
            int t = t0 + i_pre;
            int lo = t - TNO;       // inclusive (may be negative => zero spikes)
            int hi = t0 - 1;        // inclusive
            float Z = 0.f;
            int wlo = lo >> 5, whi = hi >> 5;  // arithmetic shift = floor
            for (int w = wlo; w <= whi; ++w) {
                unsigned word = (w >= 0) ? ring[(w & 15) * SUB + s_pre] : 0u;
                int bu = w * 32;
                unsigned valid = 0xFFFFFFFFu;
                if (bu < lo) valid &= (0xFFFFFFFFu << (lo - bu));
                int hb = hi - bu;
                if (hb < 31) valid &= ((1u << (hb + 1)) - 1u);
                unsigned zeros = (~word) & valid;
                while (zeros) {
                    int b = __ffs(zeros) - 1;
                    zeros &= zeros - 1u;
                    Z += k_sh[(t - (bu + b) - 1) * SUB + s_pre];
                }
            }
            Zpre[i_pre * SUB + s_pre] = Z;
            base_sh[i_pre * SUB + s_pre] = g_base[t * SUB + s_pre];
        }
        __syncthreads();

        // ---- sequential inner loop: warp 0, lane = subunit ----
        if (tid < 16) {
            int s = tid;
            unsigned myhist = 0u;  // bit j = spike at (chunk step i-1-j)
            float k0 = k0_sh[s];
            float rho0 = rho_sh[0], rho_s = rho_sh[s];
            int fast = fast_sh;
            for (int i = 0; i < CHUNK; i++) {
                unsigned intra_mask = i ? ((1u << i) - 1u) : 0u;
                unsigned zi = (~myhist) & intra_mask;
                float zsum = Zpre[i * SUB + s];
                while (zi) {
                    int b = __ffs(zi) - 1;
                    zi &= zi - 1u;
                    zsum += k_sh[b * SUB + s];
                }
                float sub = base_sh[i * SUB + s] + (k0 - zsum) + MB;
                bool sp = sub > 0.f;
                unsigned bal = __ballot_sync(0x0000FFFFu, sp);
                spikes_sh[i * SUB + s] = sp ? 1.f : 0.f;
                myhist = (myhist << 1) | (sp ? 1u : 0u);
                if (fast) {
                    // uniform-rho path: mixed states, binary injection via complement
                    float inj = rowsum_sh[s];
                    unsigned zb = (~bal) & 0xFFFFu;
                    while (zb) {
                        int b = __ffs(zb) - 1;
                        zb &= zb - 1u;
                        inj -= cw_sh[s * 17 + b];
                    }
                    float MAo = MA;
                    MB = rho0 * (MB + MAo);
                    MA = rho0 * MAo + inj;
                } else {
                    // general path: per-subunit A,B + shfl matvec
                    float Ao = A;
                    B = rho_s * (B + Ao);
                    A = rho_s * Ao + (sp ? 1.f : 0.f);
                    float accv = 0.f;
#pragma unroll
                    for (int q = 0; q < 16; q++)
                        accv += cwrow[q] * __shfl_sync(0x0000FFFFu, B, q);
                    MB = accv;
                }
            }
            ring[((t0 >> 5) & 15) * SUB + s] = __brev(myhist);
        }
        __syncthreads();
        // ---- write chunk spikes, coalesced ----
        spk_out[t0 * SUB + tid] = spikes_sh[tid];
    }
}

// ---------------- launch ----------------
extern "C" void kernel_launch(void* const* d_in, const int* in_sizes, int n_in,
                              void* d_out, int out_size)
{
    const float* S_e     = (const float*)d_in[0];
    const float* S_i     = (const float*)d_in[1];
    const float* C_den   = (const float*)d_in[2];
    const float* C_syn_e = (const float*)d_in[3];
    const float* C_syn_i = (const float*)d_in[4];
    const float* Tau_e   = (const float*)d_in[5];
    const float* Tau_i   = (const float*)d_in[6];
    const float* W_e     = (const float*)d_in[7];
    const float* W_i     = (const float*)d_in[8];
    const float* D_e     = (const float*)d_in[9];
    const float* D_i     = (const float*)d_in[10];
    const float* Tau_spk = (const float*)d_in[11];
    const float* W_spk   = (const float*)d_in[12];
    const float* W_hist  = (const float*)d_in[13];
    const float* Theta   = (const float*)d_in[14];
    float* out = (float*)d_out;
    float* out_filters = out + T_DATA * SUB;  // spk_out first, then [64,200] filters

    k_setup<<<1, 256>>>(C_den, C_syn_e, C_syn_i, Tau_e, Tau_i, W_e, W_i,
                        D_e, D_i, Tau_spk, W_spk, W_hist, out_filters);
    k_segsum<<<T_DATA / SEG_ROWS, 256>>>(S_e, S_i);
    k_conv<<<(T_DATA + TILE_T - 1) / TILE_T, 256>>>(Theta);
    k_scan<<<1, 512>>>(out);
}

// round 3
// speedup vs baseline: 1.2291x; 1.2291x over previous
#include <cuda_runtime.h>
#include <math.h>

#define T_DATA 20000
#define SUB 16
#define TNO 200
#define ENO 2000
#define INO 500
#define CHUNK 32
#define PI_F 3.14159265358979323846f

// ---------------- device scratch (no allocs allowed) ----------------
__device__ float g_syn_e[T_DATA * SUB];
__device__ float g_syn_i[T_DATA * SUB];
__device__ float g_base[T_DATA * SUB];
__device__ float g_ekT[TNO * SUB];   // [j][s]
__device__ float g_ikT[TNO * SUB];   // [j][s]
__device__ float g_hkT[TNO * SUB];   // [j][s] hist kernel
__device__ unsigned char g_seg_e[ENO];
__device__ unsigned char g_seg_i[INO];
__device__ float g_cw[SUB * SUB];    // C_den[s][q] * exp(W_spk[q]) / tau[q]
__device__ float g_rowsum[SUB];
__device__ float g_rho[SUB];
__device__ int   g_fast;

// ---------------- K0: setup ----------------
__global__ void k_setup(const float* C_den, const float* C_syn_e, const float* C_syn_i,
                        const float* Tau_e, const float* Tau_i,
                        const float* W_e, const float* W_i,
                        const float* D_e, const float* D_i,
                        const float* Tau_spk, const float* W_spk,
                        const float* W_hist, float* out_filters)
{
    int tid = threadIdx.x;
    for (int idx = tid; idx < SUB * TNO; idx += blockDim.x) {
        int s = idx / TNO, j = idx % TNO;
        float t = (float)j;
        float te  = fmaxf(t - expf(D_e[s]), 0.f);
        float tte = te / expf(Tau_e[s]);
        float ek  = tte * expf(-tte) * expf(W_e[s]);
        float ti  = fmaxf(t - expf(D_i[s]), 0.f);
        float tti = ti / expf(Tau_i[s]);
        float ik  = -tti * expf(-tti) * expf(W_i[s]);
        float tts = t / expf(Tau_spk[s]);
        float sk  = tts * expf(-tts) * expf(W_spk[s]);
        float raw = 4.0f * logf(t + 1.0f);
        float hk = 0.f;
        for (int b = 0; b < 16; b++) {
            float phi = PI_F * 0.5f * (float)b;
            float v = 0.f;
            if (!(raw < phi - PI_F || raw > phi + PI_F))
                v = 0.5f * cosf(raw - phi) + 0.5f;
            hk += W_hist[s * 16 + b] * v;
        }
        g_ekT[j * SUB + s] = ek;
        g_ikT[j * SUB + s] = ik;
        g_hkT[j * SUB + s] = hk;
        out_filters[(0  + s) * TNO + j] = ek;
        out_filters[(16 + s) * TNO + j] = ik;
        out_filters[(32 + s) * TNO + j] = sk;
        out_filters[(48 + s) * TNO + j] = hk;
    }
    for (int e = tid; e < ENO; e += blockDim.x) {
        int seg = 0;
        for (int s = 0; s < SUB; s++) if (C_syn_e[s * ENO + e] > 0.5f) seg = s;
        g_seg_e[e] = (unsigned char)seg;
    }
    for (int e = tid; e < INO; e += blockDim.x) {
        int seg = 0;
        for (int s = 0; s < SUB; s++) if (C_syn_i[s * INO + e] > 0.5f) seg = s;
        g_seg_i[e] = (unsigned char)seg;
    }
    if (tid < SUB) g_rho[tid] = expf(-1.0f / expf(Tau_spk[tid]));
    if (tid < SUB * SUB) {
        int s = tid >> 4, q = tid & 15;
        g_cw[s * SUB + q] = C_den[s * SUB + q] * expf(W_spk[q]) / expf(Tau_spk[q]);
    }
    __syncthreads();
    if (tid < SUB) {
        int s = tid;
        float rs = 0.f;
        for (int q = 0; q < SUB; q++) rs += g_cw[s * SUB + q];
        g_rowsum[s] = rs;
    }
    if (tid == 0) {
        int fast = 1;
        float r0 = g_rho[0];
        for (int s = 1; s < SUB; s++) if (g_rho[s] != r0) fast = 0;
        g_fast = fast;
    }
}

// ---------------- K1: segment sums ----------------
#define SEG_ROWS 4
__global__ void k_segsum(const float* __restrict__ S_e, const float* __restrict__ S_i)
{
    __shared__ unsigned char sege[ENO];
    __shared__ unsigned char segi[INO];
    __shared__ float acc[SEG_ROWS][32];
    int tid = threadIdx.x;
    for (int e = tid; e < ENO; e += blockDim.x) sege[e] = g_seg_e[e];
    for (int e = tid; e < INO; e += blockDim.x) segi[e] = g_seg_i[e];
    if (tid < SEG_ROWS * 32) ((float*)acc)[tid] = 0.f;
    __syncthreads();
    int t0 = blockIdx.x * SEG_ROWS;
    for (int r = 0; r < SEG_ROWS; r++) {
        const float* re = S_e + (size_t)(t0 + r) * ENO;
        for (int e = tid; e < ENO; e += blockDim.x) {
            float v = re[e];
            if (v != 0.f) atomicAdd(&acc[r][sege[e]], v);
        }
        const float* ri = S_i + (size_t)(t0 + r) * INO;
        for (int e = tid; e < INO; e += blockDim.x) {
            float v = ri[e];
            if (v != 0.f) atomicAdd(&acc[r][16 + segi[e]], v);
        }
    }
    __syncthreads();
    if (tid < SEG_ROWS * 32) {
        int r = tid >> 5, q = tid & 31;
        if (q < 16) g_syn_e[(t0 + r) * SUB + q] = acc[r][q];
        else        g_syn_i[(t0 + r) * SUB + (q - 16)] = acc[r][q];
    }
}

// ---------------- K2: causal depthwise FIR + Theta -> base ----------------
#define TILE_T 128
__global__ void k_conv(const float* __restrict__ Theta)
{
    __shared__ float se[(TILE_T + TNO) * SUB];
    __shared__ float si[(TILE_T + TNO) * SUB];
    int t0 = blockIdx.x * TILE_T;
    int tid = threadIdx.x;
    for (int idx = tid; idx < 327 * SUB; idx += blockDim.x) {
        int r = idx / SUB, s = idx % SUB;
        int tt = t0 - 200 + r;
        float ve = 0.f, vi = 0.f;
        if (tt >= 0 && tt < T_DATA) {
            ve = g_syn_e[tt * SUB + s];
            vi = g_syn_i[tt * SUB + s];
        }
        se[idx] = ve;
        si[idx] = vi;
    }
    __syncthreads();
    int s = tid & 15, tg = tid >> 4;
    float th = Theta[s];
    float acc[8];
#pragma unroll
    for (int k = 0; k < 8; k++) acc[k] = th;
    for (int j = 0; j < TNO; j++) {
        float ke = g_ekT[j * SUB + s];
        float ki = g_ikT[j * SUB + s];
#pragma unroll
        for (int k = 0; k < 8; k++) {
            int tl = tg + k * 16;
            int row = tl + 199 - j;
            acc[k] += ke * se[row * SUB + s] + ki * si[row * SUB + s];
        }
    }
#pragma unroll
    for (int k = 0; k < 8; k++) {
        int t = t0 + tg + k * 16;
        if (t < T_DATA) g_base[t * SUB + s] = acc[k];
    }
}

// ---------------- K3: sequential thresholded scan (single CTA, adaptive scans) ----------------
__global__ void __launch_bounds__(512, 1) k_scan(float* __restrict__ spk_out)
{
    __shared__ float k_sh[TNO * SUB];       // hist kernel [j][s]
    __shared__ unsigned ring[16 * SUB];     // spike bits: word w bit b = spike(32w+b)
    __shared__ float P_sh[CHUNK * SUB];     // pre-chunk hist contribution
    __shared__ float base_sh[CHUNK * SUB];
    __shared__ float spikes_sh[CHUNK * SUB];
    __shared__ float Kpre_sh[CHUNK * SUB];  // prefix sums of k (j<i)
    __shared__ float Ksuf_sh[CHUNK * SUB];  // suffix sums of k (j>=i)
    __shared__ float cw_sh[SUB * 17];
    __shared__ float rowsum_sh[SUB], rho_sh[SUB];
    __shared__ int fast_sh;

    int tid = threadIdx.x;
    for (int idx = tid; idx < TNO * SUB; idx += 512) k_sh[idx] = g_hkT[idx];
    if (tid < 256) {
        int s = tid >> 4, q = tid & 15;
        cw_sh[s * 17 + q] = g_cw[s * SUB + q];
        ring[tid] = 0u;
    }
    if (tid < SUB) {
        rowsum_sh[tid] = g_rowsum[tid];
        rho_sh[tid] = g_rho[tid];
    }
    if (tid == 0) fast_sh = g_fast;
    __syncthreads();
    // prefix/suffix sums of hist kernel (ascending order both, matching k0 reductions)
    {
        int i = tid >> 4, s = tid & 15;
        float pre = 0.f;
        for (int b = 0; b < i; b++) pre += k_sh[b * SUB + s];
        float suf = 0.f;
        for (int b = i; b < TNO; b++) suf += k_sh[b * SUB + s];
        Kpre_sh[i * SUB + s] = pre;
        Ksuf_sh[i * SUB + s] = suf;
    }
    __syncthreads();

    float MA = 0.f, MB = 0.f, A = 0.f, B = 0.f;
    float cwrow[16];
    if (tid < 16) {
#pragma unroll
        for (int q = 0; q < 16; q++) cwrow[q] = cw_sh[tid * 17 + q];
    }
    int i_pre = tid >> 4, s_pre = tid & 15;

    for (int c = 0; c < T_DATA / CHUNK; c++) {
        int t0 = c * CHUNK;
        // ---- parallel pre-phase: P[i][s] = sum over pre-chunk spikes of k[age] ----
        {
            int t = t0 + i_pre;
            int uhi = t0 - 1;
            int ulo = t - TNO; if (ulo < 0) ulo = 0;
            float P = 0.f;
            if (uhi >= ulo) {
                int wlo = ulo >> 5;
                unsigned wv[8], vv[8];
                int ones = 0, span = 0;
#pragma unroll
                for (int q8 = 0; q8 < 8; q8++) {
                    int w = wlo + q8;
                    int bu = w << 5;
                    unsigned valid = 0u;
                    if (bu <= uhi) {
                        valid = 0xFFFFFFFFu;
                        if (bu < ulo) valid <<= (ulo - bu);
                        int hb = uhi - bu;
                        if (hb < 31) valid &= ((2u << hb) - 1u);
                    }
                    unsigned word = valid ? ring[(w & 15) * SUB + s_pre] : 0u;
                    wv[q8] = word & valid;
                    vv[q8] = valid;
                    ones += __popc(wv[q8]);
                    span += __popc(valid);
                }
                if ((t >= TNO) && (2 * ones > span)) {
                    // zeros-scan (dense lane): P = Ksuf[i] - sum over clear bits
                    float acc = 0.f;
#pragma unroll
                    for (int q8 = 0; q8 < 8; q8++) {
                        unsigned zm = wv[q8] ^ vv[q8];
                        int Cw = t - 1 - ((wlo + q8) << 5);
                        while (zm) {
                            int b = __ffs(zm) - 1; zm &= zm - 1u;
                            acc += k_sh[(Cw - b) * SUB + s_pre];
                        }
                    }
                    P = Ksuf_sh[i_pre * SUB + s_pre] - acc;
                } else {
                    // ones-scan (sparse lane)
                    float acc = 0.f;
#pragma unroll
                    for (int q8 = 0; q8 < 8; q8++) {
                        unsigned om = wv[q8];
                        int Cw = t - 1 - ((wlo + q8) << 5);
                        while (om) {
                            int b = __ffs(om) - 1; om &= om - 1u;
                            acc += k_sh[(Cw - b) * SUB + s_pre];
                        }
                    }
                    P = acc;
                }
            }
            P_sh[i_pre * SUB + s_pre] = P;
            base_sh[i_pre * SUB + s_pre] = g_base[t * SUB + s_pre];
        }
        __syncthreads();

        // ---- sequential inner loop: warp 0, lane = subunit ----
        if (tid < 16) {
            int s = tid;
            unsigned myhist = 0u;  // bit j = spike at local step i-1-j
            float rho0 = rho_sh[0], rho_s = rho_sh[s];
            float rowsum = rowsum_sh[s];
            int fast = fast_sh;
            for (int i = 0; i < CHUNK; i++) {
                float Pv = P_sh[i * SUB + s];
                float bv = base_sh[i * SUB + s];
                unsigned m = i ? ((1u << i) - 1u) : 0u;
                unsigned om = myhist & m;
                float intra;
                if (2 * __popc(om) > i) {
                    unsigned zm = om ^ m;
                    float a = 0.f;
                    while (zm) { int b = __ffs(zm) - 1; zm &= zm - 1u; a += k_sh[b * SUB + s]; }
                    intra = Kpre_sh[i * SUB + s] - a;
                } else {
                    float a = 0.f;
                    while (om) { int b = __ffs(om) - 1; om &= om - 1u; a += k_sh[b * SUB + s]; }
                    intra = a;
                }
                float sub = bv + Pv + intra + MB;
                bool sp = sub > 0.f;
                unsigned bal = __ballot_sync(0x0000FFFFu, sp);
                spikes_sh[i * SUB + s] = sp ? 1.f : 0.f;
                myhist = (myhist << 1) | (sp ? 1u : 0u);
                if (fast) {
                    float inj;
                    if (__popc(bal) >= 8) {
                        inj = rowsum;
                        unsigned zb = bal ^ 0xFFFFu;
                        while (zb) { int b = __ffs(zb) - 1; zb &= zb - 1u; inj -= cw_sh[s * 17 + b]; }
                    } else {
                        inj = 0.f;
                        unsigned ob = bal;
                        while (ob) { int b = __ffs(ob) - 1; ob &= ob - 1u; inj += cw_sh[s * 17 + b]; }
                    }
                    float MAo = MA;
                    MB = rho0 * (MB + MAo);
                    MA = rho0 * MAo + inj;
                } else {
                    float Ao = A;
                    B = rho_s * (B + Ao);
                    A = rho_s * Ao + (sp ? 1.f : 0.f);
                    float accv = 0.f;
#pragma unroll
                    for (int q = 0; q < 16; q++)
                        accv += cwrow[q] * __shfl_sync(0x0000FFFFu, B, q);
                    MB = accv;
                }
            }
            ring[((t0 >> 5) & 15) * SUB + s] = __brev(myhist);
        }
        __syncthreads();
        spk_out[t0 * SUB + tid] = spikes_sh[tid];
    }
}

// ---------------- launch ----------------
extern "C" void kernel_launch(void* const* d_in, const int* in_sizes, int n_in,
                              void* d_out, int out_size)
{
    const float* S_e     = (const float*)d_in[0];
    const float* S_i     = (const float*)d_in[1];
    const float* C_den   = (const float*)d_in[2];
    const float* C_syn_e = (const float*)d_in[3];
    const float* C_syn_i = (const float*)d_in[4];
    const float* Tau_e   = (const float*)d_in[5];
    const float* Tau_i   = (const float*)d_in[6];
    const float* W_e     = (const float*)d_in[7];
    const float* W_i     = (const float*)d_in[8];
    const float* D_e     = (const float*)d_in[9];
    const float* D_i     = (const float*)d_in[10];
    const float* Tau_spk = (const float*)d_in[11];
    const float* W_spk   = (const float*)d_in[12];
    const float* W_hist  = (const float*)d_in[13];
    const float* Theta   = (const float*)d_in[14];
    float* out = (float*)d_out;
    float* out_filters = out + T_DATA * SUB;

    k_setup<<<1, 256>>>(C_den, C_syn_e, C_syn_i, Tau_e, Tau_i, W_e, W_i,
                        D_e, D_i, Tau_spk, W_spk, W_hist, out_filters);
    k_segsum<<<T_DATA / SEG_ROWS, 256>>>(S_e, S_i);
    k_conv<<<(T_DATA + TILE_T - 1) / TILE_T, 256>>>(Theta);
    k_scan<<<1, 512>>>(out);
}

// round 4
// speedup vs baseline: 2.3397x; 1.9036x over previous
#include <cuda_runtime.h>
#include <math.h>

#define T_DATA 20000
#define SUB 16
#define TNO 200
#define ENO 2000
#define INO 500
#define CHUNK 32
#define PI_F 3.14159265358979323846f

// ---------------- device scratch (no allocs allowed) ----------------
__device__ float g_syn_e[T_DATA * SUB];
__device__ float g_syn_i[T_DATA * SUB];
__device__ float g_base[T_DATA * SUB];
__device__ float g_ekT[TNO * SUB];   // [j][s]
__device__ float g_ikT[TNO * SUB];   // [j][s]
__device__ float g_hkT[TNO * SUB];   // [j][s] hist kernel
__device__ unsigned char g_seg_e[ENO];
__device__ unsigned char g_seg_i[INO];
__device__ float g_cw[SUB * SUB];    // C_den[s][q] * exp(W_spk[q]) / tau[q]
__device__ float g_rowsum[SUB];
__device__ float g_rho[SUB];
__device__ int   g_fast;

// ---------------- K0: setup ----------------
__global__ void k_setup(const float* C_den, const float* C_syn_e, const float* C_syn_i,
                        const float* Tau_e, const float* Tau_i,
                        const float* W_e, const float* W_i,
                        const float* D_e, const float* D_i,
                        const float* Tau_spk, const float* W_spk,
                        const float* W_hist, float* out_filters)
{
    int tid = threadIdx.x;
    for (int idx = tid; idx < SUB * TNO; idx += blockDim.x) {
        int s = idx / TNO, j = idx % TNO;
        float t = (float)j;
        float te  = fmaxf(t - expf(D_e[s]), 0.f);
        float tte = te / expf(Tau_e[s]);
        float ek  = tte * expf(-tte) * expf(W_e[s]);
        float ti  = fmaxf(t - expf(D_i[s]), 0.f);
        float tti = ti / expf(Tau_i[s]);
        float ik  = -tti * expf(-tti) * expf(W_i[s]);
        float tts = t / expf(Tau_spk[s]);
        float sk  = tts * expf(-tts) * expf(W_spk[s]);
        float raw = 4.0f * logf(t + 1.0f);
        float hk = 0.f;
        for (int b = 0; b < 16; b++) {
            float phi = PI_F * 0.5f * (float)b;
            float v = 0.f;
            if (!(raw < phi - PI_F || raw > phi + PI_F))
                v = 0.5f * cosf(raw - phi) + 0.5f;
            hk += W_hist[s * 16 + b] * v;
        }
        g_ekT[j * SUB + s] = ek;
        g_ikT[j * SUB + s] = ik;
        g_hkT[j * SUB + s] = hk;
        out_filters[(0  + s) * TNO + j] = ek;
        out_filters[(16 + s) * TNO + j] = ik;
        out_filters[(32 + s) * TNO + j] = sk;
        out_filters[(48 + s) * TNO + j] = hk;
    }
    for (int e = tid; e < ENO; e += blockDim.x) {
        int seg = 0;
        for (int s = 0; s < SUB; s++) if (C_syn_e[s * ENO + e] > 0.5f) seg = s;
        g_seg_e[e] = (unsigned char)seg;
    }
    for (int e = tid; e < INO; e += blockDim.x) {
        int seg = 0;
        for (int s = 0; s < SUB; s++) if (C_syn_i[s * INO + e] > 0.5f) seg = s;
        g_seg_i[e] = (unsigned char)seg;
    }
    if (tid < SUB) g_rho[tid] = expf(-1.0f / expf(Tau_spk[tid]));
    if (tid < SUB * SUB) {
        int s = tid >> 4, q = tid & 15;
        g_cw[s * SUB + q] = C_den[s * SUB + q] * expf(W_spk[q]) / expf(Tau_spk[q]);
    }
    __syncthreads();
    if (tid < SUB) {
        int s = tid;
        float rs = 0.f;
        for (int q = 0; q < SUB; q++) rs += g_cw[s * SUB + q];
        g_rowsum[s] = rs;
    }
    if (tid == 0) {
        int fast = 1;
        float r0 = g_rho[0];
        for (int s = 1; s < SUB; s++) if (g_rho[s] != r0) fast = 0;
        g_fast = fast;
    }
}

// ---------------- K1: segment sums ----------------
#define SEG_ROWS 4
__global__ void k_segsum(const float* __restrict__ S_e, const float* __restrict__ S_i)
{
    __shared__ unsigned char sege[ENO];
    __shared__ unsigned char segi[INO];
    __shared__ float acc[SEG_ROWS][32];
    int tid = threadIdx.x;
    for (int e = tid; e < ENO; e += blockDim.x) sege[e] = g_seg_e[e];
    for (int e = tid; e < INO; e += blockDim.x) segi[e] = g_seg_i[e];
    if (tid < SEG_ROWS * 32) ((float*)acc)[tid] = 0.f;
    __syncthreads();
    int t0 = blockIdx.x * SEG_ROWS;
    for (int r = 0; r < SEG_ROWS; r++) {
        const float* re = S_e + (size_t)(t0 + r) * ENO;
        for (int e = tid; e < ENO; e += blockDim.x) {
            float v = re[e];
            if (v != 0.f) atomicAdd(&acc[r][sege[e]], v);
        }
        const float* ri = S_i + (size_t)(t0 + r) * INO;
        for (int e = tid; e < INO; e += blockDim.x) {
            float v = ri[e];
            if (v != 0.f) atomicAdd(&acc[r][16 + segi[e]], v);
        }
    }
    __syncthreads();
    if (tid < SEG_ROWS * 32) {
        int r = tid >> 5, q = tid & 31;
        if (q < 16) g_syn_e[(t0 + r) * SUB + q] = acc[r][q];
        else        g_syn_i[(t0 + r) * SUB + (q - 16)] = acc[r][q];
    }
}

// ---------------- K2: causal depthwise FIR + Theta -> base ----------------
#define TILE_T 128
__global__ void k_conv(const float* __restrict__ Theta)
{
    __shared__ float se[(TILE_T + TNO) * SUB];
    __shared__ float si[(TILE_T + TNO) * SUB];
    int t0 = blockIdx.x * TILE_T;
    int tid = threadIdx.x;
    for (int idx = tid; idx < 327 * SUB; idx += blockDim.x) {
        int r = idx / SUB, s = idx % SUB;
        int tt = t0 - 200 + r;
        float ve = 0.f, vi = 0.f;
        if (tt >= 0 && tt < T_DATA) {
            ve = g_syn_e[tt * SUB + s];
            vi = g_syn_i[tt * SUB + s];
        }
        se[idx] = ve;
        si[idx] = vi;
    }
    __syncthreads();
    int s = tid & 15, tg = tid >> 4;
    float th = Theta[s];
    float acc[8];
#pragma unroll
    for (int k = 0; k < 8; k++) acc[k] = th;
    for (int j = 0; j < TNO; j++) {
        float ke = g_ekT[j * SUB + s];
        float ki = g_ikT[j * SUB + s];
#pragma unroll
        for (int k = 0; k < 8; k++) {
            int tl = tg + k * 16;
            int row = tl + 199 - j;
            acc[k] += ke * se[row * SUB + s] + ki * si[row * SUB + s];
        }
    }
#pragma unroll
    for (int k = 0; k < 8; k++) {
        int t = t0 + tg + k * 16;
        if (t < T_DATA) g_base[t * SUB + s] = acc[k];
    }
}

// ---------------- K3: chunked scan — parallel fixed-point per chunk ----------------
__global__ void __launch_bounds__(512, 1) k_scan(float* __restrict__ spk_out)
{
    __shared__ float k_sh[TNO * SUB];       // hist kernel [j][s]
    __shared__ unsigned ring[16 * SUB];     // spike bits: word w bit b = spike(32w+b)
    __shared__ float P_sh[CHUNK * SUB];     // pre-chunk hist contribution
    __shared__ float base_sh[CHUNK * SUB];
    __shared__ float spf[CHUNK * SUB];      // spike guess/solution (floats)
    __shared__ float inj_sh[CHUNK * SUB];   // per-step C_den injection
    __shared__ float Kpre_sh[CHUNK * SUB];  // prefix sums of k (fallback path)
    __shared__ float Ksuf_sh[CHUNK * SUB];  // suffix sums of k (pre-phase)
    __shared__ float cw_sh[SUB * 17];
    __shared__ float rowsum_sh[SUB], rho_sh[SUB];
    __shared__ float MA0[SUB], MB0[SUB];
    __shared__ float powt[CHUNK + 1], wt[CHUNK + 1];
    __shared__ int fast_sh;

    int tid = threadIdx.x;
    for (int idx = tid; idx < TNO * SUB; idx += 512) k_sh[idx] = g_hkT[idx];
    if (tid < 256) {
        int s = tid >> 4, q = tid & 15;
        cw_sh[s * 17 + q] = g_cw[s * SUB + q];
        ring[tid] = 0u;
    }
    if (tid < SUB) {
        rowsum_sh[tid] = g_rowsum[tid];
        rho_sh[tid] = g_rho[tid];
        MA0[tid] = 0.f; MB0[tid] = 0.f;
    }
    if (tid == 0) fast_sh = g_fast;
    spf[tid] = 0.f;
    __syncthreads();
    if (tid <= CHUNK) {
        float p = powf(rho_sh[0], (float)tid);
        powt[tid] = p;
        wt[tid] = (float)tid * p;
    }
    {
        int i = tid >> 4, s = tid & 15;
        float pre = 0.f;
        for (int b = 0; b < i; b++) pre += k_sh[b * SUB + s];
        float suf = 0.f;
        for (int b = i; b < TNO; b++) suf += k_sh[b * SUB + s];
        Kpre_sh[i * SUB + s] = pre;
        Ksuf_sh[i * SUB + s] = suf;
    }
    __syncthreads();

    // fallback-path state
    float MAr = 0.f, MBr = 0.f, A = 0.f, B = 0.f;
    float cwrow[16];
    if (tid < 16) {
#pragma unroll
        for (int q = 0; q < 16; q++) cwrow[q] = cw_sh[tid * 17 + q];
    }
    int i_pre = tid >> 4, s_pre = tid & 15;

    for (int c = 0; c < T_DATA / CHUNK; c++) {
        int t0 = c * CHUNK;
        // ---- parallel pre-phase: P[i][s] = sum over pre-chunk spikes of k[age] ----
        {
            int t = t0 + i_pre;
            int uhi = t0 - 1;
            int ulo = t - TNO; if (ulo < 0) ulo = 0;
            float P = 0.f;
            if (uhi >= ulo) {
                int wlo = ulo >> 5;
                unsigned wv[8], vv[8];
                int ones = 0, span = 0;
#pragma unroll
                for (int q8 = 0; q8 < 8; q8++) {
                    int w = wlo + q8;
                    int bu = w << 5;
                    unsigned valid = 0u;
                    if (bu <= uhi) {
                        valid = 0xFFFFFFFFu;
                        if (bu < ulo) valid <<= (ulo - bu);
                        int hb = uhi - bu;
                        if (hb < 31) valid &= ((2u << hb) - 1u);
                    }
                    unsigned word = valid ? ring[(w & 15) * SUB + s_pre] : 0u;
                    wv[q8] = word & valid;
                    vv[q8] = valid;
                    ones += __popc(wv[q8]);
                    span += __popc(valid);
                }
                if ((t >= TNO) && (2 * ones > span)) {
                    float acc = 0.f;
#pragma unroll
                    for (int q8 = 0; q8 < 8; q8++) {
                        unsigned zm = wv[q8] ^ vv[q8];
                        int Cw = t - 1 - ((wlo + q8) << 5);
                        while (zm) {
                            int b = __ffs(zm) - 1; zm &= zm - 1u;
                            acc += k_sh[(Cw - b) * SUB + s_pre];
                        }
                    }
                    P = Ksuf_sh[i_pre * SUB + s_pre] - acc;
                } else {
                    float acc = 0.f;
#pragma unroll
                    for (int q8 = 0; q8 < 8; q8++) {
                        unsigned om = wv[q8];
                        int Cw = t - 1 - ((wlo + q8) << 5);
                        while (om) {
                            int b = __ffs(om) - 1; om &= om - 1u;
                            acc += k_sh[(Cw - b) * SUB + s_pre];
                        }
                    }
                    P = acc;
                }
            }
            P_sh[i_pre * SUB + s_pre] = P;
            base_sh[i_pre * SUB + s_pre] = g_base[t * SUB + s_pre];
        }
        __syncthreads();

        if (fast_sh) {
            // ---- parallel fixed-point over the chunk ----
            int i = i_pre, s = s_pre;
            float bP = base_sh[tid] + P_sh[tid]
                     + powt[i] * MB0[s] + (float)i * powt[i] * MA0[s];
            for (int it = 0; it < 40; it++) {
                // injection from current guess (reads spf; spf stable here)
                float inj = 0.f;
#pragma unroll
                for (int q = 0; q < 16; q++)
                    inj += cw_sh[s * 17 + q] * spf[i * SUB + q];
                inj_sh[tid] = inj;
                __syncthreads();
                float acc = 0.f;
                for (int u = 0; u < i; u++) {
                    acc += wt[i - 1 - u] * inj_sh[u * SUB + s]
                         + spf[u * SUB + s] * k_sh[(i - 1 - u) * SUB + s];
                }
                float sub = bP + acc;
                float ns = sub > 0.f ? 1.f : 0.f;
                int diff = (ns != spf[tid]);
                int n = __syncthreads_count(diff);   // barrier: all reads of spf done
                spf[tid] = ns;
                __syncthreads();                      // writes visible before next reads
                if (n == 0) break;
            }
            // converged: update carried state (closed form at i = 32)
            if (tid < 16) {
                float sA = 0.f, sB = 0.f;
                for (int u = 0; u < CHUNK; u++) {
                    float v = inj_sh[u * SUB + tid];
                    sA += powt[31 - u] * v;
                    sB += wt[31 - u] * v;
                }
                float p32 = powt[CHUNK];
                float nMA = p32 * MA0[tid] + sA;
                float nMB = p32 * MB0[tid] + 32.f * p32 * MA0[tid] + sB;
                MA0[tid] = nMA;
                MB0[tid] = nMB;
                // build ring bits for this chunk
                unsigned wbits = 0u;
                for (int b = 0; b < CHUNK; b++)
                    if (spf[b * SUB + tid] != 0.f) wbits |= (1u << b);
                ring[((t0 >> 5) & 15) * SUB + tid] = wbits;
            }
            spk_out[t0 * SUB + tid] = spf[tid];
            __syncthreads();
        } else {
            // ---- general fallback: serial loop (non-uniform rho) ----
            if (tid < 16) {
                int s = tid;
                unsigned myhist = 0u;
                float rho_s = rho_sh[s];
                for (int i = 0; i < CHUNK; i++) {
                    float Pv = P_sh[i * SUB + s];
                    float bv = base_sh[i * SUB + s];
                    unsigned m = i ? ((1u << i) - 1u) : 0u;
                    unsigned om = myhist & m;
                    float intra;
                    if (2 * __popc(om) > i) {
                        unsigned zm = om ^ m;
                        float a = 0.f;
                        while (zm) { int b = __ffs(zm) - 1; zm &= zm - 1u; a += k_sh[b * SUB + s]; }
                        intra = Kpre_sh[i * SUB + s] - a;
                    } else {
                        float a = 0.f;
                        while (om) { int b = __ffs(om) - 1; om &= om - 1u; a += k_sh[b * SUB + s]; }
                        intra = a;
                    }
                    float sub = bv + Pv + intra + MBr;
                    bool sp = sub > 0.f;
                    spf[i * SUB + s] = sp ? 1.f : 0.f;
                    myhist = (myhist << 1) | (sp ? 1u : 0u);
                    float Ao = A;
                    B = rho_s * (B + Ao);
                    A = rho_s * Ao + (sp ? 1.f : 0.f);
                    float accv = 0.f;
#pragma unroll
                    for (int q = 0; q < 16; q++)
                        accv += cwrow[q] * __shfl_sync(0x0000FFFFu, B, q);
                    MBr = accv;
                }
                ring[((t0 >> 5) & 15) * SUB + s] = __brev(myhist);
            }
            __syncthreads();
            spk_out[t0 * SUB + tid] = spf[tid];
            __syncthreads();
        }
    }
    (void)MAr; (void)rowsum_sh;
}

// ---------------- launch ----------------
extern "C" void kernel_launch(void* const* d_in, const int* in_sizes, int n_in,
                              void* d_out, int out_size)
{
    const float* S_e     = (const float*)d_in[0];
    const float* S_i     = (const float*)d_in[1];
    const float* C_den   = (const float*)d_in[2];
    const float* C_syn_e = (const float*)d_in[3];
    const float* C_syn_i = (const float*)d_in[4];
    const float* Tau_e   = (const float*)d_in[5];
    const float* Tau_i   = (const float*)d_in[6];
    const float* W_e     = (const float*)d_in[7];
    const float* W_i     = (const float*)d_in[8];
    const float* D_e     = (const float*)d_in[9];
    const float* D_i     = (const float*)d_in[10];
    const float* Tau_spk = (const float*)d_in[11];
    const float* W_spk   = (const float*)d_in[12];
    const float* W_hist  = (const float*)d_in[13];
    const float* Theta   = (const float*)d_in[14];
    float* out = (float*)d_out;
    float* out_filters = out + T_DATA * SUB;

    k_setup<<<1, 256>>>(C_den, C_syn_e, C_syn_i, Tau_e, Tau_i, W_e, W_i,
                        D_e, D_i, Tau_spk, W_spk, W_hist, out_filters);
    k_segsum<<<T_DATA / SEG_ROWS, 256>>>(S_e, S_i);
    k_conv<<<(T_DATA + TILE_T - 1) / TILE_T, 256>>>(Theta);
    k_scan<<<1, 512>>>(out);
}